// round 10
// baseline (speedup 1.0000x reference)
#include <cuda_runtime.h>

#define CC   10
#define HH   30
#define WW   30
#define DD   11
#define FULL 0xFFFFFFFFu

__device__ __forceinline__ float rsum16(float v) {
    #pragma unroll
    for (int o = 1; o < 16; o <<= 1) v += __shfl_xor_sync(FULL, v, o);
    return v;
}

__global__ __launch_bounds__(32) void pve_kernel(
    const float* __restrict__ x,      // [2,10,30,30] one-hot
    const float* __restrict__ w_in,   // [33,11]
    const float* __restrict__ w_out,  // [11,11]
    const float* __restrict__ w_ff1,  // [1,11]
    const float* __restrict__ w_ff2,  // [11,1]
    const float* __restrict__ ln1_g,  // [11]
    const float* __restrict__ ln2_g,  // [11]
    float* __restrict__ out)          // [1800,10,100]
{
    __shared__ float svals[810];   // x window, [c][row][col], OOB = 0
    __shared__ float pvs[10];      // padding softmax vector (border only)

    const int lane = threadIdx.x;
    const int b    = blockIdx.x;            // pixel id 0..1799
    const int n    = b / 900;
    const int rem  = b % 900;
    const int pi   = rem / 30, pj = rem % 30;

    const bool haspad = (pi < 4) | (pi > HH - 5) | (pj < 4) | (pj > WW - 5);

    // ── hoist weight loads (border warps) to overlap staging ──
    const int d = lane;
    float kk[DD], vv[DD], wo[DD];
    float q10 = 0.f, g1 = 0.f, g2 = 0.f, f1 = 0.f, f2 = 0.f;
    if (haspad && d < DD) {
        q10 = w_in[d * DD + 10];
        g1  = ln1_g[d];
        g2  = ln2_g[d];
        f1  = w_ff1[d];
        f2  = w_ff2[d];
        #pragma unroll
        for (int c = 0; c < DD; c++) {
            kk[c] = w_in[(DD + d) * DD + c];
            vv[c] = w_in[(2 * DD + d) * DD + c];
            wo[c] = w_out[d * DD + c];
        }
    }

    // ── stage x window coalesced; fuse packed histogram (border) ──
    // k = c*81 + row*9 + col  (c<10, row,col in [0,9))
    const float* xn = x + (long)n * (CC * HH * WW);
    unsigned long long cA = 0ull, cB = 0ull;   // classes 0..5 / 6..9, 8-bit fields
    #pragma unroll
    for (int i = 0; i < 26; i++) {
        int k = lane + 32 * i;
        if (k < 810) {
            int c   = k / 81;
            int rc  = k - 81 * c;
            int row = rc / 9;
            int col = rc - 9 * row;
            int si = pi - 4 + row, sj = pj - 4 + col;
            float val = 0.f;
            if ((unsigned)si < 30u && (unsigned)sj < 30u)
                val = xn[c * 900 + si * 30 + sj];
            svals[k] = val;
            if (haspad && val > 0.5f) {
                if (c < 6) cA += 1ull << (8 * c);
                else       cB += 1ull << (8 * (c - 6));
            }
        }
    }
    __syncwarp();

    if (haspad) {
        // reduce packed histograms: every lane gets full counts
        #pragma unroll
        for (int o = 1; o < 32; o <<= 1) {
            cA += __shfl_xor_sync(FULL, cA, o);
            cB += __shfl_xor_sync(FULL, cB, o);
        }
        // in-image slot count (geometry) -> hist[10]
        int r0 = max(0, 4 - pi), r1 = min(8, 33 - pi);
        int c0 = max(0, 4 - pj), c1 = min(8, 33 - pj);
        int nIn = (r1 - r0 + 1) * (c1 - c0 + 1);
        float hf[DD];
        #pragma unroll
        for (int c = 0; c < 6; c++)  hf[c] = (float)((cA >> (8 * c)) & 0xFFull);
        #pragma unroll
        for (int c = 6; c < 10; c++) hf[c] = (float)((cB >> (8 * (c - 6))) & 0xFFull);
        hf[10] = (float)(81 - nIn);

        // attention for the padding-class query; lane d owns dim d
        float num = 0.f, den = 0.f;
        if (d < DD) {
            #pragma unroll
            for (int c = 0; c < DD; c++) {
                float e = __expf(q10 * kk[c]) * hf[c];
                den += e;
                num += e * vv[c];
            }
        }
        float ao = (d < DD) ? num / den : 0.f;

        // svec = e_10 + ao @ w_out^T
        float acc = (d == 10) ? 1.f : 0.f;
        #pragma unroll
        for (int c = 0; c < DD; c++) {
            float a = __shfl_sync(FULL, ao, c);
            if (d < DD) acc += a * wo[c];
        }
        float sv = (d < DD) ? acc : 0.f;

        // LN1
        float s1 = rsum16(sv);
        float s2 = rsum16(sv * sv);
        float m   = s1 * (1.f / 11.f);
        float var = fmaxf(s2 * (1.f / 11.f) - m * m, 0.f);
        float inv = rsqrtf(var + 1e-5f);
        float h1  = (d < DD) ? (sv - m) * inv * g1 : 0.f;

        // FF
        float tt = rsum16(h1 * f1);
        tt = fmaxf(tt, 0.f);
        float h2 = (d < DD) ? h1 + tt * f2 : 0.f;

        // LN2
        float t1 = rsum16(h2);
        float t2 = rsum16(h2 * h2);
        float m2   = t1 * (1.f / 11.f);
        float var2 = fmaxf(t2 * (1.f / 11.f) - m2 * m2, 0.f);
        float inv2 = rsqrtf(var2 + 1e-5f);
        float hhv  = (d < DD) ? (h2 - m2) * inv2 * g2 : 0.f;

        // softmax over classes 0..9 (post-LN values bounded: no max-sub)
        float ex = (d < CC) ? __expf(hhv) : 0.f;
        float se = rsum16(ex);
        if (d < CC) pvs[d] = ex / se;
    }
    __syncwarp();

    // ── scatter 250 float4: value = masked?0 : inimg? svals : padvec[c] ──
    float4* o4 = reinterpret_cast<float4*>(out + (long)b * 1000);
    #pragma unroll
    for (int it = 0; it < 8; it++) {
        int q = lane + it * 32;
        if (q < 250) {
            int c = q / 25;
            int j = q - c * 25;
            float pc = pvs[c];   // unused by interior warps (never selected)
            float4 r;
            float* rp = &r.x;
            #pragma unroll
            for (int e = 0; e < 4; e++) {
                int l  = 4 * j + e;
                int mh = l / 10, mw = l - 10 * ((l / 10));
                bool masked = (mh == 9) | (mw == 9);
                int si = pi - 4 + mh, sj = pj - 4 + mw;
                bool inimg = ((unsigned)si < 30u) & ((unsigned)sj < 30u);
                int idx = masked ? 0 : (c * 81 + mh * 9 + mw);
                float sval = svals[idx];
                rp[e] = masked ? 0.f : (inimg ? sval : pc);
            }
            o4[q] = r;
        }
    }
}

extern "C" void kernel_launch(void* const* d_in, const int* in_sizes, int n_in,
                              void* d_out, int out_size) {
    const float* x     = (const float*)d_in[0];
    const float* w_in  = (const float*)d_in[1];
    const float* w_out = (const float*)d_in[2];
    const float* w_ff1 = (const float*)d_in[3];
    const float* w_ff2 = (const float*)d_in[4];
    const float* ln1_g = (const float*)d_in[5];
    const float* ln2_g = (const float*)d_in[6];

    pve_kernel<<<1800, 32>>>(x, w_in, w_out, w_ff1, w_ff2, ln1_g, ln2_g,
                             (float*)d_out);
}